// round 12
// baseline (speedup 1.0000x reference)
#include <cuda_runtime.h>

// GridCellRouter: H=W=4096, N=16,777,216 cells, 16 iterations.
//
// (S u)[j] = sum_{i: idx[i]=j} u[i].  b_t = c_t + c_{t-1} satisfies
//   b_t = S b_{t-1} + b_{t-2},  b_0 = r, b_1 = (S+I) r;  answer A_16 = b_16.
// Even subsequence B_k = b_{2k}:  B_{k+1} = (S^2+2I) B_k - B_{k-1},
//   B_0 = r, B_1 = (S^2+S+I) r,  via composed map idx2 = idx o idx.
//
// Round 11: eliminate the 7 elementwise fix passes. Since
//   B_{k-2} = (S^2+2I) B_{k-1} - B_k   (inverse recurrence),
// the buffer being overwritten (holding dead B_{k-2}) satisfies
//   B_{k+1} = B_{k-2} + 3D + S^2 D,   D = B_k - B_{k-1},
// i.e. the whole step is ADDS ONLY -> one kernel of atomics, no
// write-before-atomic ordering, no separate fix kernel. First step uses a
// zeroed scratch; last step adds (2 cur - prev + S^2 cur) into zeroed d_out.

#define N_CELLS (4096 * 4096)

__device__ float g_x[N_CELLS];     // 64 MB
__device__ float g_y[N_CELLS];     // 64 MB
__device__ float g_z[N_CELLS];     // 64 MB
__device__ int   g_idx2[N_CELLS];  // 64 MB composed map

__device__ __forceinline__ float4 ldcs_f4(const float4* p) {
    float4 v;
    asm volatile("ld.global.cs.v4.f32 {%0,%1,%2,%3}, [%4];"
                 : "=f"(v.x), "=f"(v.y), "=f"(v.z), "=f"(v.w) : "l"(p));
    return v;
}
__device__ __forceinline__ int4 ldcs_i4(const int4* p) {
    int4 v;
    asm volatile("ld.global.cs.v4.b32 {%0,%1,%2,%3}, [%4];"
                 : "=r"(v.x), "=r"(v.y), "=r"(v.z), "=r"(v.w) : "l"(p));
    return v;
}

// idx2[i] = idx[idx[i]]
__global__ void compose_kernel(const int* __restrict__ idx,
                               int4* __restrict__ idx2, int n4) {
    int t = blockIdx.x * blockDim.x + threadIdx.x;
    if (t >= n4) return;
    int4 v = ldcs_i4(reinterpret_cast<const int4*>(idx) + t);
    int4 w;
    w.x = __ldg(idx + v.x);
    w.y = __ldg(idx + v.y);
    w.z = __ldg(idx + v.z);
    w.w = __ldg(idx + v.w);
    idx2[t] = w;
}

// X = r (pre-B1), Y = r (B_0), Z = 0, OUT = 0   (fresh every replay)
__global__ void init_kernel(const float4* __restrict__ r,
                            float4* __restrict__ x, float4* __restrict__ y,
                            float4* __restrict__ z, float4* __restrict__ out,
                            int n4) {
    int t = blockIdx.x * blockDim.x + threadIdx.x;
    if (t >= n4) return;
    float4 v = ldcs_f4(r + t);
    float4 zero = make_float4(0.f, 0.f, 0.f, 0.f);
    x[t] = v;
    y[t] = v;
    z[t] = zero;
    out[t] = zero;
}

// X += S r + S^2 r  ->  X = B_1 = (S^2+S+I) r
__global__ void b1_kernel(const float* __restrict__ r,
                          const int* __restrict__ idx,
                          const int* __restrict__ idx2,
                          float* __restrict__ x, int n4) {
    int t = blockIdx.x * blockDim.x + threadIdx.x;
    if (t >= n4) return;
    float4 c = ldcs_f4(reinterpret_cast<const float4*>(r) + t);
    int4 a = ldcs_i4(reinterpret_cast<const int4*>(idx) + t);
    int4 b = ldcs_i4(reinterpret_cast<const int4*>(idx2) + t);
    atomicAdd(x + a.x, c.x);  atomicAdd(x + a.y, c.y);
    atomicAdd(x + a.z, c.z);  atomicAdd(x + a.w, c.w);
    atomicAdd(x + b.x, c.x);  atomicAdd(x + b.y, c.y);
    atomicAdd(x + b.z, c.z);  atomicAdd(x + b.w, c.w);
}

// Zero-base step: dst(=0) += (2 cur - prev) [seq] + S^2 cur [random]
__global__ void step_zero_kernel(const float* __restrict__ cur,
                                 const float* __restrict__ prev,
                                 const int* __restrict__ idx2,
                                 float* __restrict__ dst, int n4) {
    int t = blockIdx.x * blockDim.x + threadIdx.x;
    if (t >= n4) return;
    float4 c = ldcs_f4(reinterpret_cast<const float4*>(cur) + t);
    float4 p = ldcs_f4(reinterpret_cast<const float4*>(prev) + t);
    int4 d = ldcs_i4(reinterpret_cast<const int4*>(idx2) + t);
    int b = 4 * t;
    atomicAdd(dst + b + 0, 2.f * c.x - p.x);
    atomicAdd(dst + b + 1, 2.f * c.y - p.y);
    atomicAdd(dst + b + 2, 2.f * c.z - p.z);
    atomicAdd(dst + b + 3, 2.f * c.w - p.w);
    atomicAdd(dst + d.x, c.x);  atomicAdd(dst + d.y, c.y);
    atomicAdd(dst + d.z, c.z);  atomicAdd(dst + d.w, c.w);
}

// D-step: dst(=B_{k-2}) += 3 D [seq] + S^2 D [random],  D = cur - prev
__global__ void step_d_kernel(const float* __restrict__ cur,
                              const float* __restrict__ prev,
                              const int* __restrict__ idx2,
                              float* __restrict__ dst, int n4) {
    int t = blockIdx.x * blockDim.x + threadIdx.x;
    if (t >= n4) return;
    float4 c = ldcs_f4(reinterpret_cast<const float4*>(cur) + t);
    float4 p = ldcs_f4(reinterpret_cast<const float4*>(prev) + t);
    int4 d = ldcs_i4(reinterpret_cast<const int4*>(idx2) + t);
    float4 D;
    D.x = c.x - p.x; D.y = c.y - p.y; D.z = c.z - p.z; D.w = c.w - p.w;
    int b = 4 * t;
    atomicAdd(dst + b + 0, 3.f * D.x);
    atomicAdd(dst + b + 1, 3.f * D.y);
    atomicAdd(dst + b + 2, 3.f * D.z);
    atomicAdd(dst + b + 3, 3.f * D.w);
    atomicAdd(dst + d.x, D.x);  atomicAdd(dst + d.y, D.y);
    atomicAdd(dst + d.z, D.z);  atomicAdd(dst + d.w, D.w);
}

extern "C" void kernel_launch(void* const* d_in, const int* in_sizes, int n_in,
                              void* d_out, int out_size) {
    const float* runoff = (const float*)d_in[0];
    const int* flow_idx = (const int*)d_in[1];
    float* OUT = (float*)d_out;

    float* X; float* Y; float* Z; int* idx2;
    cudaGetSymbolAddress((void**)&X, g_x);
    cudaGetSymbolAddress((void**)&Y, g_y);
    cudaGetSymbolAddress((void**)&Z, g_z);
    cudaGetSymbolAddress((void**)&idx2, g_idx2);

    const int n4 = N_CELLS / 4;                       // 4,194,304
    const int threads = 256;
    const int blocks = (n4 + threads - 1) / threads;  // 16,384

    compose_kernel<<<blocks, threads>>>(flow_idx, (int4*)idx2, n4);
    init_kernel<<<blocks, threads>>>((const float4*)runoff, (float4*)X,
                                     (float4*)Y, (float4*)Z, (float4*)OUT, n4);
    b1_kernel<<<blocks, threads>>>(runoff, flow_idx, idx2, X, n4);
    //            X = B_1, Y = B_0, Z = 0, OUT = 0

    step_zero_kernel<<<blocks, threads>>>(X, Y, idx2, Z, n4);  // Z   = B_2
    step_d_kernel<<<blocks, threads>>>(Z, X, idx2, Y, n4);     // Y   = B_3 (over B_0)
    step_d_kernel<<<blocks, threads>>>(Y, Z, idx2, X, n4);     // X   = B_4 (over B_1)
    step_d_kernel<<<blocks, threads>>>(X, Y, idx2, Z, n4);     // Z   = B_5 (over B_2)
    step_d_kernel<<<blocks, threads>>>(Z, X, idx2, Y, n4);     // Y   = B_6 (over B_3)
    step_d_kernel<<<blocks, threads>>>(Y, Z, idx2, X, n4);     // X   = B_7 (over B_4)
    step_zero_kernel<<<blocks, threads>>>(X, Y, idx2, OUT, n4);// OUT = B_8 = A_16
}

// round 14
// speedup vs baseline: 1.0698x; 1.0698x over previous
#include <cuda_runtime.h>

// GridCellRouter: H=W=4096, N=16,777,216 cells, 16 iterations.
//
// (S u)[j] = sum_{i: idx[i]=j} u[i].  b_t = c_t + c_{t-1} satisfies
//   b_t = S b_{t-1} + b_{t-2},  b_0 = r, b_1 = (S+I) r;  answer A_16 = b_16.
// Even subsequence B_k = b_{2k}:  B_{k+1} = (S^2+2I) B_k - B_{k-1},
//   B_0 = r, B_1 = (S^2+S+I) r,  via composed map idx2 = idx o idx.
// Adds-only step (round 11): dst holding dead B_{k-2} satisfies
//   B_{k+1} = B_{k-2} + 3D + S^2 D,  D = B_k - B_{k-1}.
//
// Round 13: the kernels are LSU-ISSUE-COUNT bound (~12.5us per op-per-4-elem,
// measured across rounds 10-12). Replace the 4 sequential scalar REDs with ONE
// red.global.add.v4.f32 (sm_90+): step = 8 LSU ops vs round-10's 9 (fix+scatter),
// with one launch per step instead of two.

#define N_CELLS (4096 * 4096)

__device__ float g_x[N_CELLS];     // 64 MB
__device__ float g_y[N_CELLS];     // 64 MB
__device__ float g_z[N_CELLS];     // 64 MB
__device__ int   g_idx2[N_CELLS];  // 64 MB composed map

__device__ __forceinline__ float4 ldcs_f4(const float4* p) {
    float4 v;
    asm volatile("ld.global.cs.v4.f32 {%0,%1,%2,%3}, [%4];"
                 : "=f"(v.x), "=f"(v.y), "=f"(v.z), "=f"(v.w) : "l"(p));
    return v;
}
__device__ __forceinline__ int4 ldcs_i4(const int4* p) {
    int4 v;
    asm volatile("ld.global.cs.v4.b32 {%0,%1,%2,%3}, [%4];"
                 : "=r"(v.x), "=r"(v.y), "=r"(v.z), "=r"(v.w) : "l"(p));
    return v;
}
// One-issue vector reduction: dst[0..3] += v  (16B-aligned)
__device__ __forceinline__ void red_v4(float* dst, float4 v) {
    asm volatile("red.global.add.v4.f32 [%0], {%1,%2,%3,%4};"
                 :: "l"(dst), "f"(v.x), "f"(v.y), "f"(v.z), "f"(v.w) : "memory");
}

// idx2[i] = idx[idx[i]]
__global__ void compose_kernel(const int* __restrict__ idx,
                               int4* __restrict__ idx2, int n4) {
    int t = blockIdx.x * blockDim.x + threadIdx.x;
    if (t >= n4) return;
    int4 v = ldcs_i4(reinterpret_cast<const int4*>(idx) + t);
    int4 w;
    w.x = __ldg(idx + v.x);
    w.y = __ldg(idx + v.y);
    w.z = __ldg(idx + v.z);
    w.w = __ldg(idx + v.w);
    idx2[t] = w;
}

// X = r (pre-B1), Y = r (B_0), Z = 0, OUT = 0
__global__ void init_kernel(const float4* __restrict__ r,
                            float4* __restrict__ x, float4* __restrict__ y,
                            float4* __restrict__ z, float4* __restrict__ out,
                            int n4) {
    int t = blockIdx.x * blockDim.x + threadIdx.x;
    if (t >= n4) return;
    float4 v = ldcs_f4(r + t);
    float4 zero = make_float4(0.f, 0.f, 0.f, 0.f);
    x[t] = v;
    y[t] = v;
    z[t] = zero;
    out[t] = zero;
}

// X += S r + S^2 r  ->  X = B_1 = (S^2+S+I) r
__global__ void b1_kernel(const float* __restrict__ r,
                          const int* __restrict__ idx,
                          const int* __restrict__ idx2,
                          float* __restrict__ x, int n4) {
    int t = blockIdx.x * blockDim.x + threadIdx.x;
    if (t >= n4) return;
    float4 c = ldcs_f4(reinterpret_cast<const float4*>(r) + t);
    int4 a = ldcs_i4(reinterpret_cast<const int4*>(idx) + t);
    int4 b = ldcs_i4(reinterpret_cast<const int4*>(idx2) + t);
    atomicAdd(x + a.x, c.x);  atomicAdd(x + a.y, c.y);
    atomicAdd(x + a.z, c.z);  atomicAdd(x + a.w, c.w);
    atomicAdd(x + b.x, c.x);  atomicAdd(x + b.y, c.y);
    atomicAdd(x + b.z, c.z);  atomicAdd(x + b.w, c.w);
}

// Zero-base step: dst(=0) += (2 cur - prev) [1x RED.v4] + S^2 cur [4x RED]
__global__ void step_zero_kernel(const float* __restrict__ cur,
                                 const float* __restrict__ prev,
                                 const int* __restrict__ idx2,
                                 float* __restrict__ dst, int n4) {
    int t = blockIdx.x * blockDim.x + threadIdx.x;
    if (t >= n4) return;
    float4 c = ldcs_f4(reinterpret_cast<const float4*>(cur) + t);
    float4 p = ldcs_f4(reinterpret_cast<const float4*>(prev) + t);
    int4 d = ldcs_i4(reinterpret_cast<const int4*>(idx2) + t);
    float4 s;
    s.x = 2.f * c.x - p.x;  s.y = 2.f * c.y - p.y;
    s.z = 2.f * c.z - p.z;  s.w = 2.f * c.w - p.w;
    red_v4(dst + 4 * t, s);
    atomicAdd(dst + d.x, c.x);  atomicAdd(dst + d.y, c.y);
    atomicAdd(dst + d.z, c.z);  atomicAdd(dst + d.w, c.w);
}

// D-step: dst(=B_{k-2}) += 3 D [1x RED.v4] + S^2 D [4x RED],  D = cur - prev
__global__ void step_d_kernel(const float* __restrict__ cur,
                              const float* __restrict__ prev,
                              const int* __restrict__ idx2,
                              float* __restrict__ dst, int n4) {
    int t = blockIdx.x * blockDim.x + threadIdx.x;
    if (t >= n4) return;
    float4 c = ldcs_f4(reinterpret_cast<const float4*>(cur) + t);
    float4 p = ldcs_f4(reinterpret_cast<const float4*>(prev) + t);
    int4 d = ldcs_i4(reinterpret_cast<const int4*>(idx2) + t);
    float4 D;
    D.x = c.x - p.x; D.y = c.y - p.y; D.z = c.z - p.z; D.w = c.w - p.w;
    float4 s;
    s.x = 3.f * D.x; s.y = 3.f * D.y; s.z = 3.f * D.z; s.w = 3.f * D.w;
    red_v4(dst + 4 * t, s);
    atomicAdd(dst + d.x, D.x);  atomicAdd(dst + d.y, D.y);
    atomicAdd(dst + d.z, D.z);  atomicAdd(dst + d.w, D.w);
}

extern "C" void kernel_launch(void* const* d_in, const int* in_sizes, int n_in,
                              void* d_out, int out_size) {
    const float* runoff = (const float*)d_in[0];
    const int* flow_idx = (const int*)d_in[1];
    float* OUT = (float*)d_out;

    float* X; float* Y; float* Z; int* idx2;
    cudaGetSymbolAddress((void**)&X, g_x);
    cudaGetSymbolAddress((void**)&Y, g_y);
    cudaGetSymbolAddress((void**)&Z, g_z);
    cudaGetSymbolAddress((void**)&idx2, g_idx2);

    const int n4 = N_CELLS / 4;                       // 4,194,304
    const int threads = 256;
    const int blocks = (n4 + threads - 1) / threads;  // 16,384

    compose_kernel<<<blocks, threads>>>(flow_idx, (int4*)idx2, n4);
    init_kernel<<<blocks, threads>>>((const float4*)runoff, (float4*)X,
                                     (float4*)Y, (float4*)Z, (float4*)OUT, n4);
    b1_kernel<<<blocks, threads>>>(runoff, flow_idx, idx2, X, n4);
    //            X = B_1, Y = B_0, Z = 0, OUT = 0

    step_zero_kernel<<<blocks, threads>>>(X, Y, idx2, Z, n4);  // Z   = B_2
    step_d_kernel<<<blocks, threads>>>(Z, X, idx2, Y, n4);     // Y   = B_3 (over B_0)
    step_d_kernel<<<blocks, threads>>>(Y, Z, idx2, X, n4);     // X   = B_4 (over B_1)
    step_d_kernel<<<blocks, threads>>>(X, Y, idx2, Z, n4);     // Z   = B_5 (over B_2)
    step_d_kernel<<<blocks, threads>>>(Z, X, idx2, Y, n4);     // Y   = B_6 (over B_3)
    step_d_kernel<<<blocks, threads>>>(Y, Z, idx2, X, n4);     // X   = B_7 (over B_4)
    step_zero_kernel<<<blocks, threads>>>(X, Y, idx2, OUT, n4);// OUT = B_8 = A_16
}

// round 17
// speedup vs baseline: 1.2717x; 1.1887x over previous
#include <cuda_runtime.h>

// GridCellRouter: H=W=4096, N=16,777,216 cells, 16 iterations.
//
// (S u)[j] = sum_{i: idx[i]=j} u[i].  b_t = c_t + c_{t-1} satisfies
//   b_t = S b_{t-1} + b_{t-2},  b_0 = r, b_1 = (S+I) r;  answer A_16 = b_16.
// Even subsequence B_k = b_{2k}:  B_{k+1} = (S^2+2I) B_k - B_{k-1}
//                               = [2 B_k - B_{k-1}] + S^2 B_k,
//   B_0 = r, B_1 = (S^2+S+I) r, via composed map idx2 = idx o idx.
//
// Structure = round-10 champion: per step, fix OVERWRITES dst with full-line
// stores (2 cur - prev; no dst fetch), then scatter REDs S^2 cur into it.
// 9 random-map applications is the provable minimum for this problem.
//
// Round 15 delta: pin EXACTLY the active dst in L2 (evict_last on fix's
// stores and scatter's REDs; round-2 evidence: cold scatter 113->94us).
// All loads stay .cs. Pinned set = one 64MB buffer, alternating X<->Y,
// self-displacing on rotation. Plus compose+init fused (one launch fewer).

#define N_CELLS (4096 * 4096)

__device__ float g_x[N_CELLS];     // 64 MB
__device__ float g_y[N_CELLS];     // 64 MB
__device__ int   g_idx2[N_CELLS];  // 64 MB composed map

__device__ __forceinline__ float4 ldcs_f4(const float4* p) {
    float4 v;
    asm volatile("ld.global.cs.v4.f32 {%0,%1,%2,%3}, [%4];"
                 : "=f"(v.x), "=f"(v.y), "=f"(v.z), "=f"(v.w) : "l"(p));
    return v;
}
__device__ __forceinline__ int4 ldcs_i4(const int4* p) {
    int4 v;
    asm volatile("ld.global.cs.v4.b32 {%0,%1,%2,%3}, [%4];"
                 : "=r"(v.x), "=r"(v.y), "=r"(v.z), "=r"(v.w) : "l"(p));
    return v;
}
// RED with L2::evict_last (pins the active dst buffer in L2)
__device__ __forceinline__ void red_el(float* p, float v) {
    asm volatile(
        "{ .reg .b64 pol;\n"
        "  createpolicy.fractional.L2::evict_last.b64 pol, 1.0;\n"
        "  red.global.L2::cache_hint.add.f32 [%0], %1, pol; }"
        :: "l"(p), "f"(v) : "memory");
}
// v4 store with L2::evict_last (fix establishes dst lines as pinned)
__device__ __forceinline__ void stel_f4(float4* p, float4 v) {
    asm volatile(
        "{ .reg .b64 pol;\n"
        "  createpolicy.fractional.L2::evict_last.b64 pol, 1.0;\n"
        "  st.global.L2::cache_hint.v4.f32 [%0], {%1,%2,%3,%4}, pol; }"
        :: "l"(p), "f"(v.x), "f"(v.y), "f"(v.z), "f"(v.w) : "memory");
}

// Fused: idx2[i] = idx[idx[i]];  X = r (pre-B1);  Y = r (B_0)
__global__ void compose_init_kernel(const int* __restrict__ idx,
                                    int4* __restrict__ idx2,
                                    const float4* __restrict__ r,
                                    float4* __restrict__ x,
                                    float4* __restrict__ y, int n4) {
    int t = blockIdx.x * blockDim.x + threadIdx.x;
    if (t >= n4) return;
    int4 v = ldcs_i4(reinterpret_cast<const int4*>(idx) + t);
    int4 w;
    w.x = __ldg(idx + v.x);
    w.y = __ldg(idx + v.y);
    w.z = __ldg(idx + v.z);
    w.w = __ldg(idx + v.w);
    idx2[t] = w;
    float4 rv = ldcs_f4(r + t);
    x[t] = rv;
    y[t] = rv;
}

// X += S r + S^2 r  ->  X = B_1 = (S^2+S+I) r
__global__ void b1_kernel(const float* __restrict__ r,
                          const int* __restrict__ idx,
                          const int* __restrict__ idx2,
                          float* __restrict__ x, int n4) {
    int t = blockIdx.x * blockDim.x + threadIdx.x;
    if (t >= n4) return;
    float4 c = ldcs_f4(reinterpret_cast<const float4*>(r) + t);
    int4 a = ldcs_i4(reinterpret_cast<const int4*>(idx) + t);
    int4 b = ldcs_i4(reinterpret_cast<const int4*>(idx2) + t);
    red_el(x + a.x, c.x);  red_el(x + a.y, c.y);
    red_el(x + a.z, c.z);  red_el(x + a.w, c.w);
    red_el(x + b.x, c.x);  red_el(x + b.y, c.y);
    red_el(x + b.z, c.z);  red_el(x + b.w, c.w);
}

// dst = 2*cur - prev  (full-line stores, no dst fetch; pins dst lines)
__global__ void fix_kernel(const float4* __restrict__ cur,
                           const float4* __restrict__ prev,
                           float4* __restrict__ dst, int n4) {
    int t = blockIdx.x * blockDim.x + threadIdx.x;
    if (t >= n4) return;
    float4 a = ldcs_f4(cur + t);
    float4 b = ldcs_f4(prev + t);
    float4 o;
    o.x = 2.f * a.x - b.x;  o.y = 2.f * a.y - b.y;
    o.z = 2.f * a.z - b.z;  o.w = 2.f * a.w - b.w;
    stel_f4(dst + t, o);
}

// dst[idx2[i]] += src[i]   (REDs into the L2-pinned dst)
__global__ void scatter_kernel(const float* __restrict__ src,
                               const int* __restrict__ idx2,
                               float* __restrict__ dst, int n4) {
    int t = blockIdx.x * blockDim.x + threadIdx.x;
    if (t >= n4) return;
    float4 c = ldcs_f4(reinterpret_cast<const float4*>(src) + t);
    int4 d = ldcs_i4(reinterpret_cast<const int4*>(idx2) + t);
    red_el(dst + d.x, c.x);
    red_el(dst + d.y, c.y);
    red_el(dst + d.z, c.z);
    red_el(dst + d.w, c.w);
}

extern "C" void kernel_launch(void* const* d_in, const int* in_sizes, int n_in,
                              void* d_out, int out_size) {
    const float* runoff = (const float*)d_in[0];
    const int* flow_idx = (const int*)d_in[1];
    float* OUT = (float*)d_out;

    float* X; float* Y; int* idx2;
    cudaGetSymbolAddress((void**)&X, g_x);
    cudaGetSymbolAddress((void**)&Y, g_y);
    cudaGetSymbolAddress((void**)&idx2, g_idx2);

    const int n4 = N_CELLS / 4;                       // 4,194,304
    const int threads = 256;
    const int blocks = (n4 + threads - 1) / threads;  // 16,384

    compose_init_kernel<<<blocks, threads>>>(flow_idx, (int4*)idx2,
                                             (const float4*)runoff,
                                             (float4*)X, (float4*)Y, n4);
    b1_kernel<<<blocks, threads>>>(runoff, flow_idx, idx2, X, n4);
    //            X = B_1, Y = B_0

    // 7 doubling steps: dst = 2 cur - prev; dst += S^2 cur. Last writes OUT.
    float* cur = X;
    float* prev = Y;
    for (int k = 1; k <= 7; ++k) {
        float* dst = (k == 7) ? OUT : prev;
        fix_kernel<<<blocks, threads>>>((const float4*)cur, (const float4*)prev,
                                        (float4*)dst, n4);
        scatter_kernel<<<blocks, threads>>>(cur, idx2, dst, n4);
        prev = cur;
        cur = dst;
    }
    // OUT = B_8 = b_16 = c_16 + c_15 = A_16.
}